// round 1
// baseline (speedup 1.0000x reference)
#include <cuda_runtime.h>
#include <cstdint>

// Problem constants (from reference)
#define KFRAG 8
#define SIGMA_INV 1.0e4f   // 1/SIGMA
#define GAMMA_INV 1.0e4f   // 1/GAMMA
#define ZFARV 100.0f
#define ZNEARV 1.0f
#define EPSV 1e-10f
#define MAX_F 100000

// Scratch: per-face per-vertex normals, padded to float4 for single LDG.128 each.
__device__ float4 g_facen[MAX_F * 3];

__global__ void gather_face_normals_kernel(const int* __restrict__ faces,
                                           const float* __restrict__ vn,
                                           int F) {
    int f = blockIdx.x * blockDim.x + threadIdx.x;
    if (f >= F) return;
    int v0 = faces[3 * f + 0];
    int v1 = faces[3 * f + 1];
    int v2 = faces[3 * f + 2];
    g_facen[3 * f + 0] = make_float4(vn[3 * v0], vn[3 * v0 + 1], vn[3 * v0 + 2], 0.f);
    g_facen[3 * f + 1] = make_float4(vn[3 * v1], vn[3 * v1 + 1], vn[3 * v1 + 2], 0.f);
    g_facen[3 * f + 2] = make_float4(vn[3 * v2], vn[3 * v2 + 1], vn[3 * v2 + 2], 0.f);
}

__global__ void __launch_bounds__(256)
shade_blend_kernel(const float4* __restrict__ bary,   // 6 float4 per pixel (24 f)
                   const float4* __restrict__ zbuf,   // 2 float4 per pixel
                   const float4* __restrict__ dists,  // 2 float4 per pixel
                   const int4*   __restrict__ p2f,    // 2 int4 per pixel
                   float4*       __restrict__ out,    // 1 float4 per pixel
                   int npix) {
    int p = blockIdx.x * blockDim.x + threadIdx.x;
    if (p >= npix) return;

    // Vectorized coalesced loads of all per-pixel streams.
    float b[24];
    float4* bv = reinterpret_cast<float4*>(b);
#pragma unroll
    for (int i = 0; i < 6; i++) bv[i] = bary[p * 6 + i];

    float z[KFRAG];
    reinterpret_cast<float4*>(z)[0] = zbuf[p * 2 + 0];
    reinterpret_cast<float4*>(z)[1] = zbuf[p * 2 + 1];

    float d[KFRAG];
    reinterpret_cast<float4*>(d)[0] = dists[p * 2 + 0];
    reinterpret_cast<float4*>(d)[1] = dists[p * 2 + 1];

    int f[KFRAG];
    reinterpret_cast<int4*>(f)[0] = p2f[p * 2 + 0];
    reinterpret_cast<int4*>(f)[1] = p2f[p * 2 + 1];

    float prob[KFRAG], zinv[KFRAG];
    float cx[KFRAG], cy[KFRAG], cz[KFRAG];
    float zmax = EPSV;

#pragma unroll
    for (int k = 0; k < KFRAG; k++) {
        bool m = f[k] >= 0;
        // sigmoid(-d/sigma) = 1/(1+exp(d/sigma))
        prob[k] = m ? __fdividef(1.0f, 1.0f + __expf(d[k] * SIGMA_INV)) : 0.0f;
        zinv[k] = m ? (ZFARV - z[k]) * (1.0f / (ZFARV - ZNEARV)) : 0.0f;
        zmax = fmaxf(zmax, zinv[k]);
        if (m) {
            const float4 n0 = __ldg(&g_facen[3 * f[k] + 0]);
            const float4 n1 = __ldg(&g_facen[3 * f[k] + 1]);
            const float4 n2 = __ldg(&g_facen[3 * f[k] + 2]);
            float w0 = b[3 * k + 0], w1 = b[3 * k + 1], w2 = b[3 * k + 2];
            cx[k] = w0 * n0.x + w1 * n1.x + w2 * n2.x;
            cy[k] = w0 * n0.y + w1 * n1.y + w2 * n2.y;
            cz[k] = w0 * n0.z + w1 * n1.z + w2 * n2.z;
        } else {
            cx[k] = 0.f; cy[k] = 0.f; cz[k] = 0.f;
        }
    }

    float delta = __expf((EPSV - zmax) * GAMMA_INV);
    float wsum = delta;
    // background = (1,1,1) * delta
    float ax = delta, ay = delta, az = delta;
    float one_minus = 1.0f;

#pragma unroll
    for (int k = 0; k < KFRAG; k++) {
        one_minus *= (1.0f - prob[k]);
        float w = prob[k] * __expf((zinv[k] - zmax) * GAMMA_INV);
        wsum += w;
        ax += w * cx[k];
        ay += w * cy[k];
        az += w * cz[k];
    }

    float inv = __fdividef(1.0f, wsum);
    out[p] = make_float4(ax * inv, ay * inv, az * inv, 1.0f - one_minus);
}

extern "C" void kernel_launch(void* const* d_in, const int* in_sizes, int n_in,
                              void* d_out, int out_size) {
    // metadata order: bary_coords, zbuf, dists, verts_normals, pix_to_face, faces
    const float* bary  = (const float*)d_in[0];
    const float* zbuf  = (const float*)d_in[1];
    const float* dists = (const float*)d_in[2];
    const float* vn    = (const float*)d_in[3];
    const int*   p2f   = (const int*)d_in[4];
    const int*   faces = (const int*)d_in[5];

    const int F = in_sizes[5] / 3;
    const int npix = in_sizes[1] / KFRAG;

    {
        int threads = 256;
        int blocks = (F + threads - 1) / threads;
        gather_face_normals_kernel<<<blocks, threads>>>(faces, vn, F);
    }
    {
        int threads = 256;
        int blocks = (npix + threads - 1) / threads;
        shade_blend_kernel<<<blocks, threads>>>(
            (const float4*)bary, (const float4*)zbuf, (const float4*)dists,
            (const int4*)p2f, (float4*)d_out, npix);
    }
}

// round 2
// speedup vs baseline: 1.1278x; 1.1278x over previous
#include <cuda_runtime.h>
#include <cstdint>

// Problem constants (from reference)
#define KFRAG 8
#define SIGMA_INV 1.0e4f   // 1/SIGMA
#define GAMMA_INV 1.0e4f   // 1/GAMMA
#define ZFARV 100.0f
#define ZNEARV 1.0f
#define EPSV 1e-10f
#define MAX_F 100000
#define SNORM_SCALE 32767.0f
#define SNORM_INV   (1.0f / 32767.0f)

// Packed per-face record: 9 snorm16 normal components (3 verts x 3 comps),
// padded to 32 bytes so every gather touches exactly one 32B L2 sector.
// Layout (shorts): [n0x n0y n0z n1x n1y n1z n2x n2y n2z pad...]
struct __align__(32) FaceRec {
    uint4 lo;   // 8 shorts
    uint  hi;   // 9th short (+pad)
    uint  pad[3];
};

__device__ FaceRec g_facen[MAX_F];

__device__ __forceinline__ uint pack2(float a, float b) {
    int ia = __float2int_rn(a * SNORM_SCALE);
    int ib = __float2int_rn(b * SNORM_SCALE);
    return (uint)(ia & 0xffff) | ((uint)ib << 16);
}

__global__ void gather_face_normals_kernel(const int* __restrict__ faces,
                                           const float* __restrict__ vn,
                                           int F) {
    int f = blockIdx.x * blockDim.x + threadIdx.x;
    if (f >= F) return;
    int v0 = faces[3 * f + 0];
    int v1 = faces[3 * f + 1];
    int v2 = faces[3 * f + 2];
    float n0x = vn[3 * v0], n0y = vn[3 * v0 + 1], n0z = vn[3 * v0 + 2];
    float n1x = vn[3 * v1], n1y = vn[3 * v1 + 1], n1z = vn[3 * v1 + 2];
    float n2x = vn[3 * v2], n2y = vn[3 * v2 + 1], n2z = vn[3 * v2 + 2];

    uint4 lo;
    lo.x = pack2(n0x, n0y);
    lo.y = pack2(n0z, n1x);
    lo.z = pack2(n1y, n1z);
    lo.w = pack2(n2x, n2y);
    uint hi = pack2(n2z, 0.0f);

    g_facen[f].lo = lo;
    g_facen[f].hi = hi;
}

// decode two snorm16 (raw int value; scale folded into weights)
__device__ __forceinline__ float2 s2f(uint u) {
    return make_float2((float)(int)(short)(u & 0xffffu), (float)((int)u >> 16));
}

__global__ void __launch_bounds__(256)
shade_blend_kernel(const float4* __restrict__ bary,   // 6 float4 per pixel (24 f)
                   const float4* __restrict__ zbuf,   // 2 float4 per pixel
                   const float4* __restrict__ dists,  // 2 float4 per pixel
                   const int4*   __restrict__ p2f,    // 2 int4 per pixel
                   float4*       __restrict__ out,    // 1 float4 per pixel
                   int npix) {
    int p = blockIdx.x * blockDim.x + threadIdx.x;
    if (p >= npix) return;

    // Vectorized coalesced loads of all per-pixel streams.
    float b[24];
    float4* bv = reinterpret_cast<float4*>(b);
#pragma unroll
    for (int i = 0; i < 6; i++) bv[i] = bary[p * 6 + i];

    float z[KFRAG];
    reinterpret_cast<float4*>(z)[0] = zbuf[p * 2 + 0];
    reinterpret_cast<float4*>(z)[1] = zbuf[p * 2 + 1];

    float d[KFRAG];
    reinterpret_cast<float4*>(d)[0] = dists[p * 2 + 0];
    reinterpret_cast<float4*>(d)[1] = dists[p * 2 + 1];

    int f[KFRAG];
    reinterpret_cast<int4*>(f)[0] = p2f[p * 2 + 0];
    reinterpret_cast<int4*>(f)[1] = p2f[p * 2 + 1];

    float prob[KFRAG], zinv[KFRAG];
    float cx[KFRAG], cy[KFRAG], cz[KFRAG];
    float zmax = EPSV;

#pragma unroll
    for (int k = 0; k < KFRAG; k++) {
        bool m = f[k] >= 0;
        // sigmoid(-d/sigma) = 1/(1+exp(d/sigma))
        prob[k] = m ? __fdividef(1.0f, 1.0f + __expf(d[k] * SIGMA_INV)) : 0.0f;
        zinv[k] = m ? (ZFARV - z[k]) * (1.0f / (ZFARV - ZNEARV)) : 0.0f;
        zmax = fmaxf(zmax, zinv[k]);
        if (m) {
            const FaceRec* rec = &g_facen[f[k]];
            uint4 lo = __ldg(&rec->lo);
            uint  hi = __ldg(&rec->hi);
            // scale folded into weights
            float w0 = b[3 * k + 0] * SNORM_INV;
            float w1 = b[3 * k + 1] * SNORM_INV;
            float w2 = b[3 * k + 2] * SNORM_INV;
            float2 p0 = s2f(lo.x);   // n0x n0y
            float2 p1 = s2f(lo.y);   // n0z n1x
            float2 p2 = s2f(lo.z);   // n1y n1z
            float2 p3 = s2f(lo.w);   // n2x n2y
            float  p4 = (float)(int)(short)(hi & 0xffffu);  // n2z
            cx[k] = w0 * p0.x + w1 * p1.y + w2 * p3.x;
            cy[k] = w0 * p0.y + w1 * p2.x + w2 * p3.y;
            cz[k] = w0 * p1.x + w1 * p2.y + w2 * p4;
        } else {
            cx[k] = 0.f; cy[k] = 0.f; cz[k] = 0.f;
        }
    }

    float delta = __expf((EPSV - zmax) * GAMMA_INV);
    float wsum = delta;
    // background = (1,1,1) * delta
    float ax = delta, ay = delta, az = delta;
    float one_minus = 1.0f;

#pragma unroll
    for (int k = 0; k < KFRAG; k++) {
        one_minus *= (1.0f - prob[k]);
        float w = prob[k] * __expf((zinv[k] - zmax) * GAMMA_INV);
        wsum += w;
        ax += w * cx[k];
        ay += w * cy[k];
        az += w * cz[k];
    }

    float inv = __fdividef(1.0f, wsum);
    out[p] = make_float4(ax * inv, ay * inv, az * inv, 1.0f - one_minus);
}

extern "C" void kernel_launch(void* const* d_in, const int* in_sizes, int n_in,
                              void* d_out, int out_size) {
    // metadata order: bary_coords, zbuf, dists, verts_normals, pix_to_face, faces
    const float* bary  = (const float*)d_in[0];
    const float* zbuf  = (const float*)d_in[1];
    const float* dists = (const float*)d_in[2];
    const float* vn    = (const float*)d_in[3];
    const int*   p2f   = (const int*)d_in[4];
    const int*   faces = (const int*)d_in[5];

    const int F = in_sizes[5] / 3;
    const int npix = in_sizes[1] / KFRAG;

    {
        int threads = 256;
        int blocks = (F + threads - 1) / threads;
        gather_face_normals_kernel<<<blocks, threads>>>(faces, vn, F);
    }
    {
        int threads = 256;
        int blocks = (npix + threads - 1) / threads;
        shade_blend_kernel<<<blocks, threads>>>(
            (const float4*)bary, (const float4*)zbuf, (const float4*)dists,
            (const int4*)p2f, (float4*)d_out, npix);
    }
}

// round 3
// speedup vs baseline: 1.4236x; 1.2623x over previous
#include <cuda_runtime.h>
#include <cstdint>

// Problem constants (from reference)
#define KFRAG 8
#define SIGMA_INV 1.0e4f   // 1/SIGMA
#define GAMMA_INV 1.0e4f   // 1/GAMMA
#define ZFARV 100.0f
#define ZNEARV 1.0f
#define EPSV 1e-10f
#define MAX_F 100000
#define Q14_SCALE 8191.0f
#define Q14_INV   (1.0f / 8191.0f)

// Packed per-face record, 16 bytes: components c0..c7 as 14-bit snorm at bit
// 14*i, c8 as 16-bit slot at bit 112 (value still quantized with scale 8191).
// Component order: n0x n0y n0z n1x n1y n1z n2x n2y n2z  ->  c0..c8
__device__ uint4 g_facen[MAX_F];

__device__ __forceinline__ unsigned long long q14(float a) {
    int ia = __float2int_rn(a * Q14_SCALE);
    return (unsigned long long)((unsigned)ia & 0x3FFFu);
}

__global__ void gather_face_normals_kernel(const int* __restrict__ faces,
                                           const float* __restrict__ vn,
                                           int F) {
    int f = blockIdx.x * blockDim.x + threadIdx.x;
    if (f >= F) return;
    int v0 = faces[3 * f + 0];
    int v1 = faces[3 * f + 1];
    int v2 = faces[3 * f + 2];
    float c[9];
    c[0] = vn[3 * v0]; c[1] = vn[3 * v0 + 1]; c[2] = vn[3 * v0 + 2];
    c[3] = vn[3 * v1]; c[4] = vn[3 * v1 + 1]; c[5] = vn[3 * v1 + 2];
    c[6] = vn[3 * v2]; c[7] = vn[3 * v2 + 1]; c[8] = vn[3 * v2 + 2];

    unsigned long long lo = q14(c[0]) | (q14(c[1]) << 14) | (q14(c[2]) << 28)
                          | (q14(c[3]) << 42) | ((q14(c[4]) & 0xFFull) << 56);
    unsigned long long hi = (q14(c[4]) >> 8) | (q14(c[5]) << 6) | (q14(c[6]) << 20)
                          | (q14(c[7]) << 34)
                          | ((unsigned long long)((unsigned)__float2int_rn(c[8] * Q14_SCALE) & 0xFFFFu) << 48);

    uint4 r;
    r.x = (unsigned)lo;
    r.y = (unsigned)(lo >> 32);
    r.z = (unsigned)hi;
    r.w = (unsigned)(hi >> 32);
    g_facen[f] = r;
}

__device__ __forceinline__ int sext14(unsigned v) {
    return ((int)(v << 18)) >> 18;
}

__global__ void __launch_bounds__(256, 4)
shade_blend_kernel(const float4* __restrict__ bary,   // 6 float4 per pixel (24 f)
                   const float4* __restrict__ zbuf,   // 2 float4 per pixel
                   const float4* __restrict__ dists,  // 2 float4 per pixel
                   const int4*   __restrict__ p2f,    // 2 int4 per pixel
                   float4*       __restrict__ out,    // 1 float4 per pixel
                   int npix) {
    int p = blockIdx.x * blockDim.x + threadIdx.x;
    if (p >= npix) return;

    float b[24];
    float4* bv = reinterpret_cast<float4*>(b);
#pragma unroll
    for (int i = 0; i < 6; i++) bv[i] = bary[p * 6 + i];

    float z[KFRAG];
    reinterpret_cast<float4*>(z)[0] = zbuf[p * 2 + 0];
    reinterpret_cast<float4*>(z)[1] = zbuf[p * 2 + 1];

    float d[KFRAG];
    reinterpret_cast<float4*>(d)[0] = dists[p * 2 + 0];
    reinterpret_cast<float4*>(d)[1] = dists[p * 2 + 1];

    int f[KFRAG];
    reinterpret_cast<int4*>(f)[0] = p2f[p * 2 + 0];
    reinterpret_cast<int4*>(f)[1] = p2f[p * 2 + 1];

    float prob[KFRAG], zinv[KFRAG];
    float cx[KFRAG], cy[KFRAG], cz[KFRAG];
    float zmax = EPSV;

#pragma unroll
    for (int k = 0; k < KFRAG; k++) {
        bool m = f[k] >= 0;
        int fi = m ? f[k] : 0;
        // one 16B gather per fragment, unconditional (no divergence)
        uint4 r = __ldg(&g_facen[fi]);

        // sigmoid(-d/sigma) = 1/(1+exp(d/sigma))
        prob[k] = m ? __fdividef(1.0f, 1.0f + __expf(d[k] * SIGMA_INV)) : 0.0f;
        zinv[k] = m ? (ZFARV - z[k]) * (1.0f / (ZFARV - ZNEARV)) : 0.0f;
        zmax = fmaxf(zmax, zinv[k]);

        float msel = m ? Q14_INV : 0.0f;   // quantization scale folded into weights
        float w0 = b[3 * k + 0] * msel;
        float w1 = b[3 * k + 1] * msel;
        float w2 = b[3 * k + 2] * msel;

        int c0 = sext14(r.x);
        int c1 = ((int)(r.x << 4)) >> 18;
        int c2 = sext14(__funnelshift_r(r.x, r.y, 28));
        int c3 = ((int)(r.y << 8)) >> 18;
        int c4 = sext14(__funnelshift_r(r.y, r.z, 24));
        int c5 = ((int)(r.z << 12)) >> 18;
        int c6 = sext14(__funnelshift_r(r.z, r.w, 20));
        int c7 = ((int)(r.w << 16)) >> 18;
        int c8 = ((int)r.w) >> 16;

        cx[k] = w0 * (float)c0 + w1 * (float)c3 + w2 * (float)c6;
        cy[k] = w0 * (float)c1 + w1 * (float)c4 + w2 * (float)c7;
        cz[k] = w0 * (float)c2 + w1 * (float)c5 + w2 * (float)c8;
    }

    float delta = __expf((EPSV - zmax) * GAMMA_INV);
    float wsum = delta;
    float ax = delta, ay = delta, az = delta;   // background (1,1,1)*delta
    float one_minus = 1.0f;

#pragma unroll
    for (int k = 0; k < KFRAG; k++) {
        one_minus *= (1.0f - prob[k]);
        float w = prob[k] * __expf((zinv[k] - zmax) * GAMMA_INV);
        wsum += w;
        ax += w * cx[k];
        ay += w * cy[k];
        az += w * cz[k];
    }

    float inv = __fdividef(1.0f, wsum);
    out[p] = make_float4(ax * inv, ay * inv, az * inv, 1.0f - one_minus);
}

extern "C" void kernel_launch(void* const* d_in, const int* in_sizes, int n_in,
                              void* d_out, int out_size) {
    // metadata order: bary_coords, zbuf, dists, verts_normals, pix_to_face, faces
    const float* bary  = (const float*)d_in[0];
    const float* zbuf  = (const float*)d_in[1];
    const float* dists = (const float*)d_in[2];
    const float* vn    = (const float*)d_in[3];
    const int*   p2f   = (const int*)d_in[4];
    const int*   faces = (const int*)d_in[5];

    const int F = in_sizes[5] / 3;
    const int npix = in_sizes[1] / KFRAG;

    {
        int threads = 256;
        int blocks = (F + threads - 1) / threads;
        gather_face_normals_kernel<<<blocks, threads>>>(faces, vn, F);
    }
    {
        int threads = 256;
        int blocks = (npix + threads - 1) / threads;
        shade_blend_kernel<<<blocks, threads>>>(
            (const float4*)bary, (const float4*)zbuf, (const float4*)dists,
            (const int4*)p2f, (float4*)d_out, npix);
    }
}

// round 4
// speedup vs baseline: 1.7015x; 1.1952x over previous
#include <cuda_runtime.h>
#include <cstdint>

// Problem constants (from reference)
#define SIGMA_INV 1.0e4f   // 1/SIGMA
#define GAMMA_INV 1.0e4f   // 1/GAMMA
#define ZFARV 100.0f
#define ZNEARV 1.0f
#define EPSV 1e-10f
#define MAX_F 100000
#define Q14_SCALE 8191.0f
#define Q14_INV   (1.0f / 8191.0f)

// Packed per-face record, 16 bytes: components c0..c7 as 14-bit snorm at bit
// 14*i, c8 as 16-bit slot at bit 112 (quantized with scale 8191).
// Component order: n0x n0y n0z n1x n1y n1z n2x n2y n2z  ->  c0..c8
__device__ uint4 g_facen[MAX_F];

__device__ __forceinline__ unsigned long long q14(float a) {
    int ia = __float2int_rn(a * Q14_SCALE);
    return (unsigned long long)((unsigned)ia & 0x3FFFu);
}

__global__ void gather_face_normals_kernel(const int* __restrict__ faces,
                                           const float* __restrict__ vn,
                                           int F) {
    int f = blockIdx.x * blockDim.x + threadIdx.x;
    if (f >= F) return;
    int v0 = __ldg(&faces[3 * f + 0]);
    int v1 = __ldg(&faces[3 * f + 1]);
    int v2 = __ldg(&faces[3 * f + 2]);
    float c[9];
    c[0] = vn[3 * v0]; c[1] = vn[3 * v0 + 1]; c[2] = vn[3 * v0 + 2];
    c[3] = vn[3 * v1]; c[4] = vn[3 * v1 + 1]; c[5] = vn[3 * v1 + 2];
    c[6] = vn[3 * v2]; c[7] = vn[3 * v2 + 1]; c[8] = vn[3 * v2 + 2];

    unsigned long long lo = q14(c[0]) | (q14(c[1]) << 14) | (q14(c[2]) << 28)
                          | (q14(c[3]) << 42) | ((q14(c[4]) & 0xFFull) << 56);
    unsigned long long hi = (q14(c[4]) >> 8) | (q14(c[5]) << 6) | (q14(c[6]) << 20)
                          | (q14(c[7]) << 34)
                          | ((unsigned long long)((unsigned)__float2int_rn(c[8] * Q14_SCALE) & 0xFFFFu) << 48);

    uint4 r;
    r.x = (unsigned)lo;
    r.y = (unsigned)(lo >> 32);
    r.z = (unsigned)hi;
    r.w = (unsigned)(hi >> 32);
    g_facen[f] = r;
}

__device__ __forceinline__ int sext14(unsigned v) {
    return ((int)(v << 18)) >> 18;
}

// 2 threads per pixel: thread half h in {0,1} handles fragments 4h..4h+3.
// Partial softmax-blend accumulators are combined with shfl.bfly.
__global__ void __launch_bounds__(256, 5)
shade_blend_kernel(const float4* __restrict__ bary,   // 6 float4 per pixel
                   const float4* __restrict__ zbuf,   // 2 float4 per pixel
                   const float4* __restrict__ dists,  // 2 float4 per pixel
                   const int4*   __restrict__ p2f,    // 2 int4 per pixel
                   float4*       __restrict__ out,    // 1 float4 per pixel
                   int npix) {
    int tg = blockIdx.x * blockDim.x + threadIdx.x;
    int p = tg >> 1;
    if (p >= npix) return;
    int h = tg & 1;

    // Per-half-pixel streams. z/d/f are exactly one 16B load per thread,
    // perfectly coalesced. bary is 3x float4 at 48B stride.
    float b[12];
    float4* bv = reinterpret_cast<float4*>(b);
#pragma unroll
    for (int i = 0; i < 3; i++) bv[i] = __ldcs(&bary[p * 6 + h * 3 + i]);

    float z[4]; *reinterpret_cast<float4*>(z) = __ldcs(&zbuf[p * 2 + h]);
    float d[4]; *reinterpret_cast<float4*>(d) = __ldcs(&dists[p * 2 + h]);
    int   f[4]; *reinterpret_cast<int4*>(f)   = __ldcs(&p2f[p * 2 + h]);

    float zinv[4];
    float zl = EPSV;
#pragma unroll
    for (int k = 0; k < 4; k++) {
        bool m = f[k] >= 0;
        zinv[k] = m ? (ZFARV - z[k]) * (1.0f / (ZFARV - ZNEARV)) : 0.0f;
        zl = fmaxf(zl, zinv[k]);
    }
    // full-pixel max across the thread pair
    float zmax = fmaxf(zl, __shfl_xor_sync(0xffffffffu, zl, 1));

    float ax = 0.f, ay = 0.f, az = 0.f, wsum = 0.f, om = 1.0f;

#pragma unroll
    for (int k = 0; k < 4; k++) {
        bool m = f[k] >= 0;
        int fi = m ? f[k] : 0;
        uint4 r = __ldg(&g_facen[fi]);   // one 16B gather, unconditional

        // sigmoid(-d/sigma) = 1/(1+exp(d/sigma)); masked prob -> w = 0 kills
        // any garbage color contribution, so no separate color mask needed.
        float prob = m ? __fdividef(1.0f, 1.0f + __expf(d[k] * SIGMA_INV)) : 0.0f;
        om *= (1.0f - prob);
        float w = prob * __expf((zinv[k] - zmax) * GAMMA_INV);
        wsum += w;

        float s = w * Q14_INV;           // fold weight + dequant scale
        float w0 = b[3 * k + 0] * s;
        float w1 = b[3 * k + 1] * s;
        float w2 = b[3 * k + 2] * s;

        int c0 = sext14(r.x);
        int c1 = ((int)(r.x << 4)) >> 18;
        int c2 = sext14(__funnelshift_r(r.x, r.y, 28));
        int c3 = ((int)(r.y << 8)) >> 18;
        int c4 = sext14(__funnelshift_r(r.y, r.z, 24));
        int c5 = ((int)(r.z << 12)) >> 18;
        int c6 = sext14(__funnelshift_r(r.z, r.w, 20));
        int c7 = ((int)(r.w << 16)) >> 18;
        int c8 = ((int)r.w) >> 16;

        ax += w0 * (float)c0 + w1 * (float)c3 + w2 * (float)c6;
        ay += w0 * (float)c1 + w1 * (float)c4 + w2 * (float)c7;
        az += w0 * (float)c2 + w1 * (float)c5 + w2 * (float)c8;
    }

    // combine the two half-pixel partials
    ax   += __shfl_xor_sync(0xffffffffu, ax,   1);
    ay   += __shfl_xor_sync(0xffffffffu, ay,   1);
    az   += __shfl_xor_sync(0xffffffffu, az,   1);
    wsum += __shfl_xor_sync(0xffffffffu, wsum, 1);
    om   *= __shfl_xor_sync(0xffffffffu, om,   1);

    float delta = __expf((EPSV - zmax) * GAMMA_INV);
    wsum += delta;
    float inv = __fdividef(1.0f, wsum);

    if (h == 0) {
        float4 o = make_float4((ax + delta) * inv,
                               (ay + delta) * inv,
                               (az + delta) * inv,
                               1.0f - om);
        __stcs(&out[p], o);
    }
}

extern "C" void kernel_launch(void* const* d_in, const int* in_sizes, int n_in,
                              void* d_out, int out_size) {
    // metadata order: bary_coords, zbuf, dists, verts_normals, pix_to_face, faces
    const float* bary  = (const float*)d_in[0];
    const float* zbuf  = (const float*)d_in[1];
    const float* dists = (const float*)d_in[2];
    const float* vn    = (const float*)d_in[3];
    const int*   p2f   = (const int*)d_in[4];
    const int*   faces = (const int*)d_in[5];

    const int F = in_sizes[5] / 3;
    const int npix = in_sizes[1] / 8;

    {
        int threads = 256;
        int blocks = (F + threads - 1) / threads;
        gather_face_normals_kernel<<<blocks, threads>>>(faces, vn, F);
    }
    {
        int threads = 256;
        long long nthreads = (long long)npix * 2;
        int blocks = (int)((nthreads + threads - 1) / threads);
        shade_blend_kernel<<<blocks, threads>>>(
            (const float4*)bary, (const float4*)zbuf, (const float4*)dists,
            (const int4*)p2f, (float4*)d_out, npix);
    }
}